// round 13
// baseline (speedup 1.0000x reference)
#include <cuda_runtime.h>
#include <cuda_fp16.h>
#include <cstdint>

#define C_IN 128
#define KOUT 256
#define NIMG 32
#define TIL  28                       // 28x28 tiles of 2x2 outputs
#define PT2  (NIMG*TIL*TIL)           // 25088 GEMM rows
#define VS2  ((size_t)PT2*C_IN)       // per-t V plane
#define NCH  32                       // 16 GEMMs x 2 ch-halves, K=64 each

// 2D-Winograd-transformed scratch
__device__ __align__(128) __half g_v[16 * VS2];              // [t=4i+j][p2][c]
__device__ __align__(128) __half g_u[16 * KOUT * C_IN];      // [t][k][c], i=3 negated

__constant__ int c_iord[4] = {1, 2, 0, 3};   // inner i processing order

__device__ __forceinline__ float quant16f(float v) {
    float r = rintf(v * 4096.0f);
    r = fminf(fmaxf(r, -32768.0f), 32767.0f);
    return r * (1.0f / 4096.0f);
}

__device__ __forceinline__ uint32_t su32(const void* p) {
    uint32_t a;
    asm("{ .reg .u64 t; cvta.to.shared.u64 t, %1; cvt.u32.u64 %0, t; }"
        : "=r"(a) : "l"(p));
    return a;
}

// ---------------- merged pre-kernel ----------------
// blocks [0,896): V tile-row transform, b -> (n = b/28, th = b%28)
// blocks [896,1024): U transform, 256 (k,c) elems each
#define NBLK_V 896
#define PREP_SMEM (128 * 4 * 60 * 2)   // xs[c][rr][col], col = w+1 (0..57)

__global__ void prep_all(const float* __restrict__ x, const float* __restrict__ w) {
    const int b = blockIdx.x;
    const int tid = threadIdx.x;

    if (b >= NBLK_V) {
        // ---- U = G g G^T, i=3 plane negated ----
        int idx = (b - NBLK_V) * 256 + tid;
        int k = idx >> 7, c = idx & 127;
        const float* gp = w + (size_t)k * 1152 + c * 9;
        float g[3][3];
        #pragma unroll
        for (int r = 0; r < 3; r++)
            #pragma unroll
            for (int s = 0; s < 3; s++) g[r][s] = quant16f(gp[r * 3 + s]);
        float t2[4][3];
        #pragma unroll
        for (int s = 0; s < 3; s++) {
            t2[0][s] = g[0][s];
            t2[1][s] = 0.5f * (g[0][s] + g[1][s] + g[2][s]);
            t2[2][s] = 0.5f * (g[0][s] - g[1][s] + g[2][s]);
            t2[3][s] = g[2][s];
        }
        #pragma unroll
        for (int i = 0; i < 4; i++) {
            float sgn = (i == 3) ? -1.0f : 1.0f;
            float u[4];
            u[0] = t2[i][0];
            u[1] = 0.5f * (t2[i][0] + t2[i][1] + t2[i][2]);
            u[2] = 0.5f * (t2[i][0] - t2[i][1] + t2[i][2]);
            u[3] = t2[i][2];
            #pragma unroll
            for (int j = 0; j < 4; j++)
                g_u[((size_t)((i * 4 + j) * KOUT + k)) * C_IN + c] =
                    __float2half(sgn * u[j]);
        }
        return;
    }

    // ---- V = B^T d B for one tile-row (n, th), all 128 c ----
    extern __shared__ __half xs[];   // [c][rr][col60], col = w+1
    const int n = b / TIL;
    const int th = b - n * TIL;

    // load 4 input rows (h = 2*th-1+rr), zero-padded
    {
        const int c = tid >> 1, half = tid & 1;
        #pragma unroll
        for (int rr = 0; rr < 4; rr++) {
            const int h = 2 * th - 1 + rr;
            const bool hv = (unsigned)h < 56u;
            const float* xr = x + (((size_t)n * C_IN + c) * 56 + (hv ? h : 0)) * 56;
            #pragma unroll 29
            for (int i = 0; i < 29; i++) {
                const int col = half * 29 + i;
                const int ww = col - 1;
                float v = (hv && (unsigned)ww < 56u) ? quant16f(xr[ww]) : 0.0f;
                xs[(c * 4 + rr) * 60 + col] = __float2half(v);
            }
        }
    }
    __syncthreads();

    // transform: thread -> c = tid&127, tw range (tid>>7)*14 .. +14
    const int c = tid & 127;
    const int twb = (tid >> 7) * 14;
    for (int tt = 0; tt < 14; tt++) {
        const int tw = twb + tt;
        float d[4][4];
        #pragma unroll
        for (int rr = 0; rr < 4; rr++)
            #pragma unroll
            for (int s = 0; s < 4; s++)
                d[rr][s] = __half2float(xs[(c * 4 + rr) * 60 + 2 * tw + s]);
        float t1[4][4];
        #pragma unroll
        for (int s = 0; s < 4; s++) {
            t1[0][s] = d[0][s] - d[2][s];
            t1[1][s] = d[1][s] + d[2][s];
            t1[2][s] = d[2][s] - d[1][s];
            t1[3][s] = d[1][s] - d[3][s];
        }
        const size_t p2 = (size_t)(n * TIL + th) * TIL + tw;
        #pragma unroll
        for (int i = 0; i < 4; i++) {
            float v0 = t1[i][0] - t1[i][2];
            float v1 = t1[i][1] + t1[i][2];
            float v2 = t1[i][2] - t1[i][1];
            float v3 = t1[i][1] - t1[i][3];
            g_v[(i * 4 + 0) * VS2 + p2 * C_IN + c] = __float2half(v0);
            g_v[(i * 4 + 1) * VS2 + p2 * C_IN + c] = __float2half(v1);
            g_v[(i * 4 + 2) * VS2 + p2 * C_IN + c] = __float2half(v2);
            g_v[(i * 4 + 3) * VS2 + p2 * C_IN + c] = __float2half(v3);
        }
    }
}

// ---------------- main kernel: 64Mx128N CTA, 8 warps(32x32), occ 1 ----------------
// smem stages: 4 x (A 8KB [64 p2 x 128B] + B 16KB [128 k x 128B]) = 96KB
// epilogue: float4 [128 n][65] = 133120 B (reuses same smem)
#define A_ST(s) ((s) * 24576u)
#define B_ST(s) ((s) * 24576u + 8192u)
#define SMEM_TOTAL 133120

__device__ __forceinline__ void cp16(uint32_t dst, const void* src) {
    asm volatile("cp.async.cg.shared.global [%0], [%1], 16;"
                 :: "r"(dst), "l"(src) : "memory");
}

__device__ __forceinline__ void ldsm4(uint32_t* r, uint32_t addr) {
    asm volatile("ldmatrix.sync.aligned.m8n8.x4.shared.b16 {%0,%1,%2,%3}, [%4];"
                 : "=r"(r[0]), "=r"(r[1]), "=r"(r[2]), "=r"(r[3]) : "r"(addr));
}

__device__ __forceinline__ void mma16816(float* c, const uint32_t* a,
                                         uint32_t b0, uint32_t b1) {
    asm volatile(
        "mma.sync.aligned.m16n8k16.row.col.f32.f16.f16.f32 "
        "{%0,%1,%2,%3}, {%4,%5,%6,%7}, {%8,%9}, {%0,%1,%2,%3};"
        : "+f"(c[0]), "+f"(c[1]), "+f"(c[2]), "+f"(c[3])
        : "r"(a[0]), "r"(a[1]), "r"(a[2]), "r"(a[3]), "r"(b0), "r"(b1));
}

__global__ __launch_bounds__(256, 1) void conv_wino2(float* __restrict__ out) {
    extern __shared__ char smem[];
    const uint32_t sb = su32(smem);
    const int tid = threadIdx.x;
    const int wid = tid >> 5, lane = tid & 31;
    const int wm = wid & 1, wn = wid >> 1;       // warp tile: 32m x 32n
    const unsigned p0 = blockIdx.x << 6;
    const int n0 = blockIdx.y << 7;

    // A staging: row = tid>>2 (64 rows x 128B), 32B quarter = tid&3 (2 cp16)
    const int rowA = tid >> 2, qA = tid & 3;
    // B staging: row = tid>>1 (128 rows x 128B), 64B half = tid&1 (4 cp16)
    const int rowB = tid >> 1, halfB = tid & 1;

    auto issue = [&](int kc) {
        const int st = kc & 3;
        const int g = kc >> 1;
        const int ch0 = (kc & 1) << 6;
        const int tsel = c_iord[g & 3] * 4 + (g >> 2);   // t = i*4 + j
        const __half* asrc = g_v + (size_t)tsel * VS2
                             + (size_t)(p0 + rowA) * C_IN + ch0 + qA * 16;
        #pragma unroll
        for (int j = 0; j < 2; j++) {
            const uint32_t gg = qA * 2 + j;
            const uint32_t sw = (gg ^ (rowA & 7)) << 4;
            cp16(sb + A_ST(st) + rowA * 128 + sw, asrc + j * 8);
        }
        const __half* bsrc = g_u + ((size_t)(tsel * KOUT + n0 + rowB)) * C_IN
                             + ch0 + halfB * 32;
        #pragma unroll
        for (int j = 0; j < 4; j++) {
            const uint32_t gg = halfB * 4 + j;
            const uint32_t sw = (gg ^ (rowB & 7)) << 4;
            cp16(sb + B_ST(st) + rowB * 128 + sw, bsrc + j * 8);
        }
        asm volatile("cp.async.commit_group;" ::: "memory");
    };

    // 6 accumulator sets: Y[0..3] = (i',j') = (0,0),(0,1),(1,0),(1,1); W[0..1] working
    float Y[4][2][4][4], W[2][2][4][4];
    #pragma unroll
    for (int q = 0; q < 4; q++)
        #pragma unroll
        for (int a = 0; a < 2; a++)
            #pragma unroll
            for (int bq = 0; bq < 4; bq++)
                #pragma unroll
                for (int cq = 0; cq < 4; cq++) Y[q][a][bq][cq] = 0.f;

    auto run2 = [&](int g, float (&acc)[2][4][4]) {
        for (int sub = 0; sub < 2; sub++) {
            const int kc = g * 2 + sub;
            asm volatile("cp.async.wait_group 2;" ::: "memory");
            __syncthreads();
            if (kc + 3 < NCH) issue(kc + 3);
            else asm volatile("cp.async.commit_group;" ::: "memory");

            const uint32_t Ab = sb + A_ST(kc & 3);
            const uint32_t Bb = sb + B_ST(kc & 3);
            #pragma unroll
            for (int stp = 0; stp < 4; stp++) {
                uint32_t ar[2][4], br[2][4];
                #pragma unroll
                for (int mt = 0; mt < 2; mt++) {
                    const int row = wm * 32 + mt * 16 + (lane & 7) + ((lane >> 3) & 1) * 8;
                    const int grp = 2 * stp + (lane >> 4);
                    ldsm4(ar[mt], Ab + row * 128 + ((grp ^ (row & 7)) << 4));
                }
                #pragma unroll
                for (int bt = 0; bt < 2; bt++) {
                    const int row = wn * 32 + bt * 16 + (lane & 7) + (lane >> 4) * 8;
                    const int grp = 2 * stp + ((lane >> 3) & 1);
                    ldsm4(br[bt], Bb + row * 128 + ((grp ^ (row & 7)) << 4));
                }
                #pragma unroll
                for (int mt = 0; mt < 2; mt++)
                    #pragma unroll
                    for (int nt = 0; nt < 4; nt++)
                        mma16816(acc[mt][nt], ar[mt],
                                 br[nt >> 1][(nt & 1) * 2], br[nt >> 1][(nt & 1) * 2 + 1]);
            }
        }
    };

    issue(0); issue(1); issue(2);

    for (int jj = 0; jj < 4; jj++) {
        // zero W0
        #pragma unroll
        for (int a = 0; a < 2; a++)
            #pragma unroll
            for (int bq = 0; bq < 4; bq++)
                #pragma unroll
                for (int cq = 0; cq < 4; cq++) W[0][a][bq][cq] = 0.f;

        run2(jj * 4 + 0, W[0]);          // i=1: W0 = m1j
        #pragma unroll
        for (int a = 0; a < 2; a++)
            #pragma unroll
            for (int bq = 0; bq < 4; bq++)
                #pragma unroll
                for (int cq = 0; cq < 4; cq++) W[1][a][bq][cq] = W[0][a][bq][cq];
        run2(jj * 4 + 1, W[0]);          // i=2: W0 = m1j + m2j
        #pragma unroll
        for (int a = 0; a < 2; a++)
            #pragma unroll
            for (int bq = 0; bq < 4; bq++)
                #pragma unroll
                for (int cq = 0; cq < 4; cq++)
                    W[1][a][bq][cq] = 2.0f * W[1][a][bq][cq] - W[0][a][bq][cq];
        run2(jj * 4 + 2, W[0]);          // i=0: W0 = T0j
        run2(jj * 4 + 3, W[1]);          // i=3 (U negated): W1 = T1j

        // fold T.j into Y with A-matrix signs (Y.0: j=0,1,2 [+]; Y.1: j=1[+],2[-],3[-])
        const float s0 = (jj <= 2) ? 1.0f : 0.0f;
        const float s1 = (jj == 1) ? 1.0f : ((jj >= 2) ? -1.0f : 0.0f);
        #pragma unroll
        for (int a = 0; a < 2; a++)
            #pragma unroll
            for (int bq = 0; bq < 4; bq++)
                #pragma unroll
                for (int cq = 0; cq < 4; cq++) {
                    Y[0][a][bq][cq] += s0 * W[0][a][bq][cq];
                    Y[1][a][bq][cq] += s1 * W[0][a][bq][cq];
                    Y[2][a][bq][cq] += s0 * W[1][a][bq][cq];
                    Y[3][a][bq][cq] += s1 * W[1][a][bq][cq];
                }
    }

    asm volatile("cp.async.wait_group 0;" ::: "memory");
    __syncthreads();

    // ---- epilogue: float4(y00,y01,y10,y11) -> smem [128 n][65] -> stores ----
    float4* eb4 = (float4*)smem;
    {
        const int r = lane >> 2, ccol = (lane & 3) * 2;
        #pragma unroll
        for (int mt = 0; mt < 2; mt++)
            #pragma unroll
            for (int nt = 0; nt < 4; nt++) {
                const int m = wm * 32 + mt * 16 + r;
                const int nn = wn * 32 + nt * 8 + ccol;
                eb4[nn * 65 + m] =
                    make_float4(Y[0][mt][nt][0], Y[1][mt][nt][0], Y[2][mt][nt][0], Y[3][mt][nt][0]);
                eb4[(nn + 1) * 65 + m] =
                    make_float4(Y[0][mt][nt][1], Y[1][mt][nt][1], Y[2][mt][nt][1], Y[3][mt][nt][1]);
                eb4[nn * 65 + m + 8] =
                    make_float4(Y[0][mt][nt][2], Y[1][mt][nt][2], Y[2][mt][nt][2], Y[3][mt][nt][2]);
                eb4[(nn + 1) * 65 + m + 8] =
                    make_float4(Y[0][mt][nt][3], Y[1][mt][nt][3], Y[2][mt][nt][3], Y[3][mt][nt][3]);
            }
    }
    __syncthreads();
    for (int it = 0; it < 32; it++) {
        const int flat = tid + it * 256;
        const int k = flat >> 6;
        const int m = flat & 63;
        const float4 v = eb4[k * 65 + m];
        const unsigned pp = p0 + m;
        const unsigned ni = pp / (TIL * TIL);
        const unsigned rr = pp - ni * (TIL * TIL);
        const unsigned th = rr / TIL;
        const unsigned tw = rr - th * TIL;
        float* o = out + ((size_t)(ni * KOUT + n0 + k) * 56 + 2 * th) * 56 + 2 * tw;
        *(float2*)o        = make_float2(v.x, v.y);
        *(float2*)(o + 56) = make_float2(v.z, v.w);
    }
}

extern "C" void kernel_launch(void* const* d_in, const int* in_sizes, int n_in,
                              void* d_out, int out_size) {
    const float* x = (const float*)d_in[0];
    const float* w = (const float*)d_in[1];
    float* out = (float*)d_out;

    cudaFuncSetAttribute(prep_all, cudaFuncAttributeMaxDynamicSharedMemorySize,
                         PREP_SMEM);
    cudaFuncSetAttribute(conv_wino2, cudaFuncAttributeMaxDynamicSharedMemorySize,
                         SMEM_TOTAL);

    prep_all<<<NBLK_V + 128, 256, PREP_SMEM>>>(x, w);
    dim3 grid(PT2 / 64, KOUT / 128);
    conv_wino2<<<grid, 256, SMEM_TOTAL>>>(out);
}

// round 14
// speedup vs baseline: 1.0786x; 1.0786x over previous
#include <cuda_runtime.h>
#include <cuda_fp16.h>
#include <cstdint>

#define C_IN 128
#define KOUT 256
#define NIMG 32
#define TIL  28                       // 28x28 tiles of 2x2 outputs
#define PT2  (NIMG*TIL*TIL)           // 25088 GEMM rows
#define VS2  ((size_t)PT2*C_IN)       // per-t V plane
#define NCH  32                       // 16 GEMMs x 2 ch-halves, K=64 each

// 2D-Winograd-transformed scratch
__device__ __align__(128) __half g_v[16 * VS2];              // [t=4i+j][p2][c]
__device__ __align__(128) __half g_u[16 * KOUT * C_IN];      // [t][k][c], i=3 negated

__constant__ int c_iord[4] = {1, 2, 0, 3};   // inner i processing order

__device__ __forceinline__ float quant16f(float v) {
    float r = rintf(v * 4096.0f);
    r = fminf(fmaxf(r, -32768.0f), 32767.0f);
    return r * (1.0f / 4096.0f);
}

__device__ __forceinline__ uint32_t su32(const void* p) {
    uint32_t a;
    asm("{ .reg .u64 t; cvta.to.shared.u64 t, %1; cvt.u32.u64 %0, t; }"
        : "=r"(a) : "l"(p));
    return a;
}

// ---------------- pre-kernels ----------------
// V: blocks [0, 3584): b -> (th = b%28, cb = (b/28)%4, n = b/112)
//    each handles 32 c x 4 rows x 58 cols -> 28 tiles x 32 c
// U: blocks [3584, 3584+128)
#define NBLK_V 3584
#define PREP_SMEM (4 * 58 * 33 * 4)    // xs[rr][col][c] floats, stride 33

__global__ void prep_all(const float* __restrict__ x, const float* __restrict__ w) {
    const int b = blockIdx.x;
    const int tid = threadIdx.x;

    if (b >= NBLK_V) {
        // ---- U = G g G^T, i=3 planes negated ----
        int idx = (b - NBLK_V) * 256 + tid;
        int k = idx >> 7, c = idx & 127;
        const float* gp = w + (size_t)k * 1152 + c * 9;
        float g[3][3];
        #pragma unroll
        for (int r = 0; r < 3; r++)
            #pragma unroll
            for (int s = 0; s < 3; s++) g[r][s] = quant16f(gp[r * 3 + s]);
        float t2[4][3];
        #pragma unroll
        for (int s = 0; s < 3; s++) {
            t2[0][s] = g[0][s];
            t2[1][s] = 0.5f * (g[0][s] + g[1][s] + g[2][s]);
            t2[2][s] = 0.5f * (g[0][s] - g[1][s] + g[2][s]);
            t2[3][s] = g[2][s];
        }
        #pragma unroll
        for (int i = 0; i < 4; i++) {
            float sgn = (i == 3) ? -1.0f : 1.0f;
            float u[4];
            u[0] = t2[i][0];
            u[1] = 0.5f * (t2[i][0] + t2[i][1] + t2[i][2]);
            u[2] = 0.5f * (t2[i][0] - t2[i][1] + t2[i][2]);
            u[3] = t2[i][2];
            #pragma unroll
            for (int j = 0; j < 4; j++)
                g_u[((size_t)((i * 4 + j) * KOUT + k)) * C_IN + c] =
                    __float2half(sgn * u[j]);
        }
        return;
    }

    // ---- V = B^T d B: one (n, th, c-block of 32) ----
    extern __shared__ float xs[];      // [(rr*58 + col)*33 + c]
    const int th = b % TIL;
    const int cb = (b / TIL) & 3;
    const int n  = b / (TIL * 4);
    const int wid = tid >> 5, lane = tid & 31;

    // load: 128 rows (c32 x rr4) x 58 cols, lane = col (conflict-free, stride 33)
    #pragma unroll 4
    for (int it = 0; it < 16; it++) {
        const int ri = wid + it * 8;       // 0..127
        const int c = ri >> 2, rr = ri & 3;
        const int h = 2 * th - 1 + rr;
        const bool hv = (unsigned)h < 56u;
        const float* xr = x + (((size_t)n * C_IN + cb * 32 + c) * 56 + (hv ? h : 0)) * 56;
        #pragma unroll
        for (int ps = 0; ps < 2; ps++) {
            const int col = lane + ps * 29;
            if (lane < 29) {
                const int ww = col - 1;
                float v = (hv && (unsigned)ww < 56u) ? quant16f(xr[ww]) : 0.0f;
                xs[(rr * 58 + col) * 33 + c] = v;
            }
        }
    }
    __syncthreads();

    // transform: lane = c (conflict-free), tw = (tid>>5) + g*8
    const int c = tid & 31;
    const int twb = tid >> 5;
    for (int g = 0; g < 4; g++) {
        const int tw = twb + g * 8;
        if (tw >= TIL) break;
        float d[4][4];
        #pragma unroll
        for (int rr = 0; rr < 4; rr++)
            #pragma unroll
            for (int s = 0; s < 4; s++)
                d[rr][s] = xs[(rr * 58 + 2 * tw + s) * 33 + c];
        float t1[4][4];
        #pragma unroll
        for (int s = 0; s < 4; s++) {
            t1[0][s] = d[0][s] - d[2][s];
            t1[1][s] = d[1][s] + d[2][s];
            t1[2][s] = d[2][s] - d[1][s];
            t1[3][s] = d[1][s] - d[3][s];
        }
        const size_t p2 = (size_t)(n * TIL + th) * TIL + tw;
        #pragma unroll
        for (int i = 0; i < 4; i++) {
            g_v[(i * 4 + 0) * VS2 + p2 * C_IN + cb * 32 + c] =
                __float2half(t1[i][0] - t1[i][2]);
            g_v[(i * 4 + 1) * VS2 + p2 * C_IN + cb * 32 + c] =
                __float2half(t1[i][1] + t1[i][2]);
            g_v[(i * 4 + 2) * VS2 + p2 * C_IN + cb * 32 + c] =
                __float2half(t1[i][2] - t1[i][1]);
            g_v[(i * 4 + 3) * VS2 + p2 * C_IN + cb * 32 + c] =
                __float2half(t1[i][1] - t1[i][3]);
        }
    }
}

// ---------------- main kernel: 32Mx128N CTA, 8 warps(16x32), 2 CTAs/SM ----------------
// smem stages: 4 x (A 4KB [32 p2 x 128B] + B 16KB [128 k x 128B]) = 80KB
#define A_ST(s) ((s) * 20480u)
#define B_ST(s) ((s) * 20480u + 4096u)
#define SMEM_TOTAL 81920

__device__ __forceinline__ void cp16(uint32_t dst, const void* src) {
    asm volatile("cp.async.cg.shared.global [%0], [%1], 16;"
                 :: "r"(dst), "l"(src) : "memory");
}

__device__ __forceinline__ void ldsm4(uint32_t* r, uint32_t addr) {
    asm volatile("ldmatrix.sync.aligned.m8n8.x4.shared.b16 {%0,%1,%2,%3}, [%4];"
                 : "=r"(r[0]), "=r"(r[1]), "=r"(r[2]), "=r"(r[3]) : "r"(addr));
}

__device__ __forceinline__ void mma16816(float* c, const uint32_t* a,
                                         uint32_t b0, uint32_t b1) {
    asm volatile(
        "mma.sync.aligned.m16n8k16.row.col.f32.f16.f16.f32 "
        "{%0,%1,%2,%3}, {%4,%5,%6,%7}, {%8,%9}, {%0,%1,%2,%3};"
        : "+f"(c[0]), "+f"(c[1]), "+f"(c[2]), "+f"(c[3])
        : "r"(a[0]), "r"(a[1]), "r"(a[2]), "r"(a[3]), "r"(b0), "r"(b1));
}

__global__ __launch_bounds__(256, 2) void conv_wino2(float* __restrict__ out) {
    extern __shared__ char smem[];
    const uint32_t sb = su32(smem);
    const int tid = threadIdx.x;
    const int wid = tid >> 5, lane = tid & 31;
    const int wm = wid & 1, wn = wid >> 1;       // warp tile: 16m x 32n
    const unsigned p0 = blockIdx.x << 5;
    const int n0 = blockIdx.y << 7;

    // A staging: row = tid>>3 (32 rows x 128B), 16B group = tid&7 (1 cp16)
    const int rowA = tid >> 3, gA = tid & 7;
    // B staging: row = tid>>1 (128 rows x 128B), 64B half = tid&1 (4 cp16)
    const int rowB = tid >> 1, halfB = tid & 1;

    auto issue = [&](int kc) {
        const int st = kc & 3;
        const int g = kc >> 1;
        const int ch0 = (kc & 1) << 6;
        const int tsel = c_iord[g & 3] * 4 + (g >> 2);   // t = i*4 + j
        const __half* asrc = g_v + (size_t)tsel * VS2
                             + (size_t)(p0 + rowA) * C_IN + ch0 + gA * 8;
        cp16(sb + A_ST(st) + rowA * 128 + (((uint32_t)gA ^ (rowA & 7)) << 4), asrc);
        const __half* bsrc = g_u + ((size_t)(tsel * KOUT + n0 + rowB)) * C_IN
                             + ch0 + halfB * 32;
        #pragma unroll
        for (int j = 0; j < 4; j++) {
            const uint32_t gg = halfB * 4 + j;
            cp16(sb + B_ST(st) + rowB * 128 + ((gg ^ (rowB & 7)) << 4), bsrc + j * 8);
        }
        asm volatile("cp.async.commit_group;" ::: "memory");
    };

    // 6 accumulator sets of 16: Y[4] outputs + W[2] working
    float Y[4][4][4], W[2][4][4];
    #pragma unroll
    for (int q = 0; q < 4; q++)
        #pragma unroll
        for (int bq = 0; bq < 4; bq++)
            #pragma unroll
            for (int cq = 0; cq < 4; cq++) Y[q][bq][cq] = 0.f;

    auto run2 = [&](int g, float (&acc)[4][4]) {
        for (int sub = 0; sub < 2; sub++) {
            const int kc = g * 2 + sub;
            asm volatile("cp.async.wait_group 2;" ::: "memory");
            __syncthreads();
            if (kc + 3 < NCH) issue(kc + 3);
            else asm volatile("cp.async.commit_group;" ::: "memory");

            const uint32_t Ab = sb + A_ST(kc & 3);
            const uint32_t Bb = sb + B_ST(kc & 3);
            #pragma unroll
            for (int stp = 0; stp < 4; stp++) {
                uint32_t ar[4], br[2][4];
                {
                    const int row = wm * 16 + (lane & 15);
                    const int grp = 2 * stp + (lane >> 4);
                    ldsm4(ar, Ab + row * 128 + ((grp ^ (row & 7)) << 4));
                }
                #pragma unroll
                for (int bt = 0; bt < 2; bt++) {
                    const int row = wn * 32 + bt * 16 + (lane & 7) + (lane >> 4) * 8;
                    const int grp = 2 * stp + ((lane >> 3) & 1);
                    ldsm4(br[bt], Bb + row * 128 + ((grp ^ (row & 7)) << 4));
                }
                #pragma unroll
                for (int nt = 0; nt < 4; nt++)
                    mma16816(acc[nt], ar,
                             br[nt >> 1][(nt & 1) * 2], br[nt >> 1][(nt & 1) * 2 + 1]);
            }
        }
    };

    issue(0); issue(1); issue(2);

    for (int jj = 0; jj < 4; jj++) {
        #pragma unroll
        for (int bq = 0; bq < 4; bq++)
            #pragma unroll
            for (int cq = 0; cq < 4; cq++) W[0][bq][cq] = 0.f;

        run2(jj * 4 + 0, W[0]);          // i=1: W0 = m1j
        #pragma unroll
        for (int bq = 0; bq < 4; bq++)
            #pragma unroll
            for (int cq = 0; cq < 4; cq++) W[1][bq][cq] = W[0][bq][cq];
        run2(jj * 4 + 1, W[0]);          // i=2: W0 = m1j + m2j
        #pragma unroll
        for (int bq = 0; bq < 4; bq++)
            #pragma unroll
            for (int cq = 0; cq < 4; cq++)
                W[1][bq][cq] = 2.0f * W[1][bq][cq] - W[0][bq][cq];   // m1j - m2j
        run2(jj * 4 + 2, W[0]);          // i=0: W0 = T0j
        run2(jj * 4 + 3, W[1]);          // i=3 (U negated): W1 = T1j

        const float s0 = (jj <= 2) ? 1.0f : 0.0f;
        const float s1 = (jj == 1) ? 1.0f : ((jj >= 2) ? -1.0f : 0.0f);
        #pragma unroll
        for (int bq = 0; bq < 4; bq++)
            #pragma unroll
            for (int cq = 0; cq < 4; cq++) {
                Y[0][bq][cq] += s0 * W[0][bq][cq];
                Y[1][bq][cq] += s1 * W[0][bq][cq];
                Y[2][bq][cq] += s0 * W[1][bq][cq];
                Y[3][bq][cq] += s1 * W[1][bq][cq];
            }
    }

    asm volatile("cp.async.wait_group 0;" ::: "memory");
    __syncthreads();

    // ---- epilogue: float4(y00,y01,y10,y11) -> smem [128 n][33] -> stores ----
    float4* eb4 = (float4*)smem;
    {
        const int r = lane >> 2, ccol = (lane & 3) * 2;
        #pragma unroll
        for (int nt = 0; nt < 4; nt++) {
            const int m = wm * 16 + r;
            const int nn = wn * 32 + nt * 8 + ccol;
            eb4[nn * 33 + m] =
                make_float4(Y[0][nt][0], Y[1][nt][0], Y[2][nt][0], Y[3][nt][0]);
            eb4[(nn + 1) * 33 + m] =
                make_float4(Y[0][nt][1], Y[1][nt][1], Y[2][nt][1], Y[3][nt][1]);
            eb4[nn * 33 + m + 8] =
                make_float4(Y[0][nt][2], Y[1][nt][2], Y[2][nt][2], Y[3][nt][2]);
            eb4[(nn + 1) * 33 + m + 8] =
                make_float4(Y[0][nt][3], Y[1][nt][3], Y[2][nt][3], Y[3][nt][3]);
        }
    }
    __syncthreads();
    #pragma unroll
    for (int it = 0; it < 16; it++) {
        const int flat = tid + it * 256;
        const int k = flat >> 5;
        const int m = flat & 31;
        const float4 v = eb4[k * 33 + m];
        const unsigned pp = p0 + m;
        const unsigned ni = pp / (TIL * TIL);
        const unsigned rr = pp - ni * (TIL * TIL);
        const unsigned th = rr / TIL;
        const unsigned tw = rr - th * TIL;
        float* o = out + ((size_t)(ni * KOUT + n0 + k) * 56 + 2 * th) * 56 + 2 * tw;
        *(float2*)o        = make_float2(v.x, v.y);
        *(float2*)(o + 56) = make_float2(v.z, v.w);
    }
}

extern "C" void kernel_launch(void* const* d_in, const int* in_sizes, int n_in,
                              void* d_out, int out_size) {
    const float* x = (const float*)d_in[0];
    const float* w = (const float*)d_in[1];
    float* out = (float*)d_out;

    cudaFuncSetAttribute(prep_all, cudaFuncAttributeMaxDynamicSharedMemorySize,
                         PREP_SMEM);
    cudaFuncSetAttribute(conv_wino2, cudaFuncAttributeMaxDynamicSharedMemorySize,
                         SMEM_TOTAL);

    prep_all<<<NBLK_V + 128, 256, PREP_SMEM>>>(x, w);
    dim3 grid(PT2 / 32, KOUT / 128);
    conv_wino2<<<grid, 256, SMEM_TOTAL>>>(out);
}